// round 12
// baseline (speedup 1.0000x reference)
#include <cuda_runtime.h>
#include <cuda_bf16.h>
#include <math.h>
#include <stdint.h>

// Problem constants
#define BB      2
#define TT      2048
#define NH      16
#define HD      128
#define NE      2048
#define QKV_LD  2304
#define MROWS   (BB*TT)         // 4096
#define KDIM    2048

// Scratch (__device__ globals; no allocation allowed)
__device__ __nv_bfloat16 g_xh[(size_t)MROWS * NE];
__device__ __nv_bfloat16 g_xl[(size_t)MROWS * NE];
__device__ __nv_bfloat16 g_wah[(size_t)QKV_LD * NE];
__device__ __nv_bfloat16 g_wal[(size_t)QKV_LD * NE];
__device__ __nv_bfloat16 g_woh[(size_t)NE * NE];
__device__ __nv_bfloat16 g_wol[(size_t)NE * NE];
__device__ __nv_bfloat16 g_ath[(size_t)MROWS * NE];
__device__ __nv_bfloat16 g_atl[(size_t)MROWS * NE];
// flash inputs (post-rope, pre-split)
__device__ __nv_bfloat16 g_qh[(size_t)MROWS * NE];   // Q pre-scaled hi
__device__ __nv_bfloat16 g_ql[(size_t)MROWS * NE];   // Q pre-scaled lo
__device__ __nv_bfloat16 g_kh[(size_t)MROWS * HD];
__device__ __nv_bfloat16 g_kl[(size_t)MROWS * HD];
__device__ __nv_bfloat16 g_vth[(size_t)BB * HD * TT];  // V^T [b][d][key]
__device__ __nv_bfloat16 g_vtl[(size_t)BB * HD * TT];
// RoPE trig table [t][j]
__device__ float g_cost[(size_t)TT * 64];
__device__ float g_sint[(size_t)TT * 64];

// ---------------------------------------------------------------------------
// Helpers
// ---------------------------------------------------------------------------
__device__ __forceinline__ uint32_t smem_u32(const void* p) {
    uint32_t a;
    asm("{ .reg .u64 t; cvta.to.shared.u64 t, %1; cvt.u32.u64 %0, t; }"
        : "=r"(a) : "l"(p));
    return a;
}

__device__ __forceinline__ void ldsm_x4(uint32_t& r0, uint32_t& r1,
                                        uint32_t& r2, uint32_t& r3,
                                        uint32_t addr) {
    asm volatile("ldmatrix.sync.aligned.m8n8.x4.shared.b16 {%0,%1,%2,%3}, [%4];"
                 : "=r"(r0), "=r"(r1), "=r"(r2), "=r"(r3) : "r"(addr));
}

__device__ __forceinline__ void mma_16816(float* d, const uint32_t* a,
                                          const uint32_t* b) {
    asm volatile(
        "mma.sync.aligned.m16n8k16.row.col.f32.bf16.bf16.f32 "
        "{%0,%1,%2,%3}, {%4,%5,%6,%7}, {%8,%9}, {%0,%1,%2,%3};"
        : "+f"(d[0]), "+f"(d[1]), "+f"(d[2]), "+f"(d[3])
        : "r"(a[0]), "r"(a[1]), "r"(a[2]), "r"(a[3]), "r"(b[0]), "r"(b[1]));
}

#define CP_ASYNC16(dst, src) \
    asm volatile("cp.async.cg.shared.global [%0], [%1], 16;" :: "r"(dst), "l"(src))

// split (a,b) -> hi bf16x2 and lo bf16x2 packed as u32 (low half = a)
__device__ __forceinline__ void split2(float a, float b, uint32_t& h, uint32_t& l) {
    __nv_bfloat16 ha = __float2bfloat16(a), hb = __float2bfloat16(b);
    float ra = a - __bfloat162float(ha);
    float rb = b - __bfloat162float(hb);
    __nv_bfloat162 hv(ha, hb);
    __nv_bfloat162 lv(__float2bfloat16(ra), __float2bfloat16(rb));
    h = *(uint32_t*)&hv;
    l = *(uint32_t*)&lv;
}

// ---------------------------------------------------------------------------
// Split fp32 -> (hi, lo) bf16 (x, w_attn, w_out)
// ---------------------------------------------------------------------------
__global__ __launch_bounds__(256) void split_kernel(const float* __restrict__ src,
                                                    __nv_bfloat16* __restrict__ hi,
                                                    __nv_bfloat16* __restrict__ lo,
                                                    int n4) {
    int i = blockIdx.x * 256 + threadIdx.x;
    if (i >= n4) return;
    float4 v = ((const float4*)src)[i];
    uint32_t h0, l0, h1, l1;
    split2(v.x, v.y, h0, l0);
    split2(v.z, v.w, h1, l1);
    ((uint2*)hi)[i] = make_uint2(h0, h1);
    ((uint2*)lo)[i] = make_uint2(l0, l1);
}

// ---------------------------------------------------------------------------
// RoPE trig table: pos[j] = 10000 ** (-(4j+1)/128)  (verified round 3)
// ---------------------------------------------------------------------------
__global__ __launch_bounds__(64) void trig_kernel() {
    const int t = blockIdx.x;
    const int j = threadIdx.x;
    double e = ((-4.0 * (double)j - 1.0) / 128.0) * 9.210340371976184;
    float freq = (float)exp(e);
    float ang = (float)t * freq;
    g_cost[t * 64 + j] = cosf(ang);
    g_sint[t * 64 + j] = sinf(ang);
}

// ---------------------------------------------------------------------------
// GEMM mainloop shared macro-structure (verified round 11):
// CTA tile 256(M)x128(N), K-tile 64, 256 threads, 8 warps 4(M)x2(N),
// warp tile 64x64. C = Ah*Bh + Al*Bh + Ah*Bl. 2-stage cp.async.
// ---------------------------------------------------------------------------
#define GKT 64
#define ROWB 144
#define A_TILE_B (256 * ROWB)            // 36864
#define B_TILE_B (128 * ROWB)            // 18432
#define STAGE_B (2 * A_TILE_B + 2 * B_TILE_B)   // 110592
#define GEMM_SMEM (2 * STAGE_B)          // 221184

#define GEMM_MAINLOOP(K_)                                                     \
    auto load_stage = [&](int s, int kt) {                                    \
        const uint32_t st = sbase0 + s * STAGE_B;                             \
        _Pragma("unroll")                                                     \
        for (int i = 0; i < 8; i++) {                                         \
            const int f = i * 256 + tid;                                      \
            const int r = f >> 3;                                             \
            const int c = f & 7;                                              \
            CP_ASYNC16(st + r * ROWB + c * 16,                                \
                       gAh + (size_t)r * (K_) + kt * GKT + c * 8);            \
            CP_ASYNC16(st + A_TILE_B + r * ROWB + c * 16,                     \
                       gAl + (size_t)r * (K_) + kt * GKT + c * 8);            \
        }                                                                     \
        _Pragma("unroll")                                                     \
        for (int i = 0; i < 4; i++) {                                         \
            const int f = i * 256 + tid;                                      \
            const int r = f >> 3;                                             \
            const int c = f & 7;                                              \
            CP_ASYNC16(st + 2 * A_TILE_B + r * ROWB + c * 16,                 \
                       gBh + (size_t)r * (K_) + kt * GKT + c * 8);            \
            CP_ASYNC16(st + 2 * A_TILE_B + B_TILE_B + r * ROWB + c * 16,      \
                       gBl + (size_t)r * (K_) + kt * GKT + c * 8);            \
        }                                                                     \
        asm volatile("cp.async.commit_group;" ::: "memory");                  \
    };                                                                        \
    float acc[32][4];                                                         \
    _Pragma("unroll")                                                         \
    for (int t = 0; t < 32; t++)                                              \
        _Pragma("unroll")                                                     \
        for (int j = 0; j < 4; j++) acc[t][j] = 0.0f;                         \
    const int mat = lane >> 3;                                                \
    const int nkt = (K_) / GKT;                                               \
    load_stage(0, 0);                                                         \
    for (int kt = 0; kt < nkt; kt++) {                                        \
        const int s = kt & 1;                                                 \
        if (kt + 1 < nkt) {                                                   \
            load_stage((kt + 1) & 1, kt + 1);                                 \
            asm volatile("cp.async.wait_group 1;" ::: "memory");              \
        } else {                                                              \
            asm volatile("cp.async.wait_group 0;" ::: "memory");              \
        }                                                                     \
        __syncthreads();                                                      \
        const uint32_t st = sbase0 + s * STAGE_B;                             \
        const uint32_t aBh = st + (wm * 64) * ROWB;                           \
        const uint32_t aBl = aBh + A_TILE_B;                                  \
        const uint32_t bBh = st + 2 * A_TILE_B + (wn * 64) * ROWB;            \
        const uint32_t bBl = bBh + B_TILE_B;                                  \
        _Pragma("unroll")                                                     \
        for (int ks = 0; ks < 4; ks++) {                                      \
            const uint32_t kc = ks * 32 + (lane >> 4) * 16;                   \
            uint32_t ah[4][4], al[4][4];                                      \
            _Pragma("unroll")                                                 \
            for (int mi = 0; mi < 4; mi++) {                                  \
                uint32_t ao = (mi * 16 + (lane & 15)) * ROWB + kc;            \
                ldsm_x4(ah[mi][0], ah[mi][1], ah[mi][2], ah[mi][3], aBh + ao);\
                ldsm_x4(al[mi][0], al[mi][1], al[mi][2], al[mi][3], aBl + ao);\
            }                                                                 \
            const uint32_t bo = ((mat >> 1) * 8 + (lane & 7)) * ROWB          \
                              + ks * 32 + (mat & 1) * 16;                     \
            {                                                                 \
                uint32_t bh[8][2];                                            \
                _Pragma("unroll")                                             \
                for (int g = 0; g < 4; g++) {                                 \
                    uint32_t o = g * 16 * ROWB + bo;                          \
                    ldsm_x4(bh[2 * g][0], bh[2 * g][1], bh[2 * g + 1][0],     \
                            bh[2 * g + 1][1], bBh + o);                       \
                }                                                             \
                _Pragma("unroll")                                             \
                for (int mi = 0; mi < 4; mi++)                                \
                    _Pragma("unroll")                                         \
                    for (int nj = 0; nj < 8; nj++) {                          \
                        mma_16816(acc[mi * 8 + nj], ah[mi], bh[nj]);          \
                        mma_16816(acc[mi * 8 + nj], al[mi], bh[nj]);          \
                    }                                                         \
            }                                                                 \
            {                                                                 \
                uint32_t bl[8][2];                                            \
                _Pragma("unroll")                                             \
                for (int g = 0; g < 4; g++) {                                 \
                    uint32_t o = g * 16 * ROWB + bo;                          \
                    ldsm_x4(bl[2 * g][0], bl[2 * g][1], bl[2 * g + 1][0],     \
                            bl[2 * g + 1][1], bBl + o);                       \
                }                                                             \
                _Pragma("unroll")                                             \
                for (int mi = 0; mi < 4; mi++)                                \
                    _Pragma("unroll")                                         \
                    for (int nj = 0; nj < 8; nj++)                            \
                        mma_16816(acc[mi * 8 + nj], ah[mi], bl[nj]);          \
            }                                                                 \
        }                                                                     \
        __syncthreads();                                                      \
    }

// ---------------------------------------------------------------------------
// Plain GEMM (used for GEMM2): C output fp32.
// ---------------------------------------------------------------------------
__global__ __launch_bounds__(256, 1) void gemm_bf16x3(
    const __nv_bfloat16* __restrict__ Ah, const __nv_bfloat16* __restrict__ Al,
    const __nv_bfloat16* __restrict__ Bh, const __nv_bfloat16* __restrict__ Bl,
    float* __restrict__ C, int ldc, int K) {
    extern __shared__ char dynsmem[];
    const uint32_t sbase0 = smem_u32(dynsmem);

    const int tid = threadIdx.x;
    const int lane = tid & 31;
    const int warp = tid >> 5;
    const int wm = warp & 3;
    const int wn = warp >> 2;
    const int m0 = blockIdx.y * 256;
    const int n0 = blockIdx.x * 128;

    const __nv_bfloat16* gAh = Ah + (size_t)m0 * K;
    const __nv_bfloat16* gAl = Al + (size_t)m0 * K;
    const __nv_bfloat16* gBh = Bh + (size_t)n0 * K;
    const __nv_bfloat16* gBl = Bl + (size_t)n0 * K;

    GEMM_MAINLOOP(K)

    const int rbase = m0 + wm * 64 + (lane >> 2);
    const int cbase = n0 + wn * 64 + (lane & 3) * 2;
#pragma unroll
    for (int mi = 0; mi < 4; mi++)
#pragma unroll
        for (int nj = 0; nj < 8; nj++) {
            float* c0 = C + (size_t)(rbase + mi * 16) * ldc + cbase + nj * 8;
            float* c1 = c0 + 8 * ldc;
            *(float2*)c0 = make_float2(acc[mi * 8 + nj][0], acc[mi * 8 + nj][1]);
            *(float2*)c1 = make_float2(acc[mi * 8 + nj][2], acc[mi * 8 + nj][3]);
        }
}

// ---------------------------------------------------------------------------
// GEMM1 fused: qkv = x @ w_attn^T with fused RoPE/scale/split epilogue.
// blockIdx.x: 0-15 = q head tiles, 16 = k tile, 17 = v tile.
// acc staged to smem fp32 [256][133], then per-tile-type postprocess.
// ---------------------------------------------------------------------------
#define SEPI 133

__global__ __launch_bounds__(256, 1) void gemm1_fused(
    const __nv_bfloat16* __restrict__ Ah, const __nv_bfloat16* __restrict__ Al,
    const __nv_bfloat16* __restrict__ Bh, const __nv_bfloat16* __restrict__ Bl) {
    extern __shared__ char dynsmem[];
    const uint32_t sbase0 = smem_u32(dynsmem);

    const int tid = threadIdx.x;
    const int lane = tid & 31;
    const int warp = tid >> 5;
    const int wm = warp & 3;
    const int wn = warp >> 2;
    const int m0 = blockIdx.y * 256;
    const int n0 = blockIdx.x * 128;
    const int K = KDIM;

    const __nv_bfloat16* gAh = Ah + (size_t)m0 * K;
    const __nv_bfloat16* gAl = Al + (size_t)m0 * K;
    const __nv_bfloat16* gBh = Bh + (size_t)n0 * K;
    const __nv_bfloat16* gBl = Bl + (size_t)n0 * K;

    GEMM_MAINLOOP(K)

    // ---- stage acc to smem fp32 (mainloop smem dead after trailing sync) ----
    float* se = (float*)dynsmem;
    __syncthreads();
    {
        const int rb = wm * 64 + (lane >> 2);
        const int cb = wn * 64 + (lane & 3) * 2;
#pragma unroll
        for (int mi = 0; mi < 4; mi++)
#pragma unroll
            for (int nj = 0; nj < 8; nj++) {
                int r = rb + mi * 16, c = cb + nj * 8;
                se[r * SEPI + c]           = acc[mi * 8 + nj][0];
                se[r * SEPI + c + 1]       = acc[mi * 8 + nj][1];
                se[(r + 8) * SEPI + c]     = acc[mi * 8 + nj][2];
                se[(r + 8) * SEPI + c + 1] = acc[mi * 8 + nj][3];
            }
    }
    __syncthreads();

    const int bx = blockIdx.x;
    const int bb = m0 >> 11;               // batch
    const int tx = tid & 63;
    const int ty = tid >> 6;               // 0..3

    if (bx < 17) {
        // q heads (scaled) and k (unscaled): RoPE + hi/lo split
        const bool isq = (bx < 16);
        const float sc = 0.08838834764831845f;
        for (int r = ty; r < 256; r += 4) {
            const int t = (m0 + r) & (TT - 1);
            float cv = g_cost[t * 64 + tx];
            float sv = g_sint[t * 64 + tx];
            float x1 = se[r * SEPI + tx];
            float x2 = se[r * SEPI + tx + 64];
            float r1 = x1 * cv - x2 * sv;
            float r2 = x2 * cv + x1 * sv;
            if (isq) {
                r1 *= sc; r2 *= sc;
                __nv_bfloat16 h1 = __float2bfloat16(r1);
                __nv_bfloat16 h2 = __float2bfloat16(r2);
                size_t o = (size_t)(m0 + r) * NE + bx * 128 + tx;
                g_qh[o]      = h1;
                g_qh[o + 64] = h2;
                g_ql[o]      = __float2bfloat16(r1 - __bfloat162float(h1));
                g_ql[o + 64] = __float2bfloat16(r2 - __bfloat162float(h2));
            } else {
                __nv_bfloat16 h1 = __float2bfloat16(r1);
                __nv_bfloat16 h2 = __float2bfloat16(r2);
                size_t o = (size_t)(m0 + r) * HD + tx;
                g_kh[o]      = h1;
                g_kh[o + 64] = h2;
                g_kl[o]      = __float2bfloat16(r1 - __bfloat162float(h1));
                g_kl[o + 64] = __float2bfloat16(r2 - __bfloat162float(h2));
            }
        }
    } else {
        // v tile: transpose + hi/lo split -> [b][d][key]
        const int m0t = m0 & (TT - 1);
        for (int d0 = ty; d0 < 128; d0 += 4) {
            size_t orow = ((size_t)bb * HD + d0) * TT + m0t;
#pragma unroll
            for (int kb2 = 0; kb2 < 4; kb2++) {
                int key = kb2 * 64 + tx;
                float v = se[key * SEPI + d0];
                __nv_bfloat16 h = __float2bfloat16(v);
                g_vth[orow + key] = h;
                g_vtl[orow + key] = __float2bfloat16(v - __bfloat162float(h));
            }
        }
    }
}

// ---------------------------------------------------------------------------
// MMA flash MQA (verified round 6)
// ---------------------------------------------------------------------------
#define CKEYS 64
#define NCH (TT / CKEYS)
#define QROWB 272
#define KROWB 272
#define VROWB 144
#define QTILE_B (128 * QROWB)
#define KTILE_B (CKEYS * KROWB)
#define VTILE_B (HD * VROWB)
#define FSTAGE_B (2 * KTILE_B + 2 * VTILE_B)
#define FLASH_SMEM (2 * QTILE_B + 2 * FSTAGE_B)

__global__ __launch_bounds__(256, 1) void mqa_flash_mma() {
    extern __shared__ char fsm[];
    const uint32_t sb = smem_u32(fsm);
    const int tid = threadIdx.x;
    const int lane = tid & 31;
    const int warp = tid >> 5;
    const int b = blockIdx.z;
    const int h = blockIdx.y;
    const int m0 = blockIdx.x * 128;

    {
        const __nv_bfloat16* gq = g_qh + (size_t)(b * TT + m0) * NE + h * 128;
        const __nv_bfloat16* gl = g_ql + (size_t)(b * TT + m0) * NE + h * 128;
#pragma unroll
        for (int i = 0; i < 8; i++) {
            int f = i * 256 + tid;
            int r = f >> 4;
            int c = f & 15;
            uint4 vh = *(const uint4*)(gq + (size_t)r * NE + c * 8);
            uint4 vl = *(const uint4*)(gl + (size_t)r * NE + c * 8);
            *(uint4*)(fsm + r * QROWB + c * 16) = vh;
            *(uint4*)(fsm + QTILE_B + r * QROWB + c * 16) = vl;
        }
    }

    auto load_stage = [&](int s, int kb) {
        uint32_t st = sb + 2 * QTILE_B + s * FSTAGE_B;
        const __nv_bfloat16* kh = g_kh + (size_t)(b * TT + kb * CKEYS) * HD;
        const __nv_bfloat16* kl = g_kl + (size_t)(b * TT + kb * CKEYS) * HD;
#pragma unroll
        for (int i = 0; i < 4; i++) {
            int f = i * 256 + tid;
            int r = f >> 4;
            int c = f & 15;
            CP_ASYNC16(st + r * KROWB + c * 16, kh + (size_t)r * HD + c * 8);
            CP_ASYNC16(st + KTILE_B + r * KROWB + c * 16, kl + (size_t)r * HD + c * 8);
        }
        const __nv_bfloat16* vh = g_vth + (size_t)b * HD * TT + kb * CKEYS;
        const __nv_bfloat16* vl = g_vtl + (size_t)b * HD * TT + kb * CKEYS;
#pragma unroll
        for (int i = 0; i < 4; i++) {
            int f = i * 256 + tid;
            int r = f >> 3;
            int c = f & 7;
            CP_ASYNC16(st + 2 * KTILE_B + r * VROWB + c * 16,
                       vh + (size_t)r * TT + c * 8);
            CP_ASYNC16(st + 2 * KTILE_B + VTILE_B + r * VROWB + c * 16,
                       vl + (size_t)r * TT + c * 8);
        }
        asm volatile("cp.async.commit_group;" ::: "memory");
    };

    float oacc[16][4];
#pragma unroll
    for (int t = 0; t < 16; t++)
#pragma unroll
        for (int j = 0; j < 4; j++) oacc[t][j] = 0.0f;
    float m_i[2] = {-INFINITY, -INFINITY};
    float l_i[2] = {0.0f, 0.0f};

    load_stage(0, 0);

    for (int kb = 0; kb < NCH; kb++) {
        const int s = kb & 1;
        if (kb + 1 < NCH) {
            load_stage((kb + 1) & 1, kb + 1);
            asm volatile("cp.async.wait_group 1;" ::: "memory");
        } else {
            asm volatile("cp.async.wait_group 0;" ::: "memory");
        }
        __syncthreads();

        const uint32_t st = sb + 2 * QTILE_B + s * FSTAGE_B;
        const int mat = lane >> 3;

        float sfr[8][4];
#pragma unroll
        for (int t = 0; t < 8; t++)
#pragma unroll
            for (int j = 0; j < 4; j++) sfr[t][j] = 0.0f;

#pragma unroll
        for (int ks = 0; ks < 8; ks++) {
            uint32_t ao = (warp * 16 + (lane & 15)) * QROWB
                        + ks * 32 + (lane >> 4) * 16;
            uint32_t ah[4], al[4];
            ldsm_x4(ah[0], ah[1], ah[2], ah[3], sb + ao);
            ldsm_x4(al[0], al[1], al[2], al[3], sb + QTILE_B + ao);

            uint32_t bo = ((mat >> 1) * 8 + (lane & 7)) * KROWB
                        + ks * 32 + (mat & 1) * 16;
            uint32_t bh[8][2], bl[8][2];
#pragma unroll
            for (int g = 0; g < 4; g++) {
                uint32_t o = g * 16 * KROWB + bo;
                ldsm_x4(bh[2 * g][0], bh[2 * g][1], bh[2 * g + 1][0],
                        bh[2 * g + 1][1], st + o);
                ldsm_x4(bl[2 * g][0], bl[2 * g][1], bl[2 * g + 1][0],
                        bl[2 * g + 1][1], st + KTILE_B + o);
            }
#pragma unroll
            for (int nj = 0; nj < 8; nj++) {
                mma_16816(sfr[nj], ah, bh[nj]);
                mma_16816(sfr[nj], ah, bl[nj]);
                mma_16816(sfr[nj], al, bh[nj]);
            }
        }

#pragma unroll
        for (int half = 0; half < 2; half++) {
            float mx = -INFINITY;
#pragma unroll
            for (int nj = 0; nj < 8; nj++)
                mx = fmaxf(mx, fmaxf(sfr[nj][2 * half], sfr[nj][2 * half + 1]));
            mx = fmaxf(mx, __shfl_xor_sync(0xffffffffu, mx, 1));
            mx = fmaxf(mx, __shfl_xor_sync(0xffffffffu, mx, 2));
            float mn = fmaxf(m_i[half], mx);
            float corr = __expf(m_i[half] - mn);
            m_i[half] = mn;
            float sum = 0.0f;
#pragma unroll
            for (int nj = 0; nj < 8; nj++) {
                float p0 = __expf(sfr[nj][2 * half] - mn);
                float p1 = __expf(sfr[nj][2 * half + 1] - mn);
                sfr[nj][2 * half] = p0;
                sfr[nj][2 * half + 1] = p1;
                sum += p0 + p1;
            }
            sum += __shfl_xor_sync(0xffffffffu, sum, 1);
            sum += __shfl_xor_sync(0xffffffffu, sum, 2);
            l_i[half] = l_i[half] * corr + sum;
#pragma unroll
            for (int nt = 0; nt < 16; nt++) {
                oacc[nt][2 * half] *= corr;
                oacc[nt][2 * half + 1] *= corr;
            }
        }

        const uint32_t vbh = st + 2 * KTILE_B;
        const uint32_t vbl = vbh + VTILE_B;
#pragma unroll
        for (int kk = 0; kk < 4; kk++) {
            uint32_t ph[4], pl[4];
            split2(sfr[2 * kk][0], sfr[2 * kk][1], ph[0], pl[0]);
            split2(sfr[2 * kk][2], sfr[2 * kk][3], ph[1], pl[1]);
            split2(sfr[2 * kk + 1][0], sfr[2 * kk + 1][1], ph[2], pl[2]);
            split2(sfr[2 * kk + 1][2], sfr[2 * kk + 1][3], ph[3], pl[3]);

            uint32_t bo = ((mat >> 1) * 8 + (lane & 7)) * VROWB
                        + kk * 32 + (mat & 1) * 16;
#pragma unroll
            for (int g = 0; g < 8; g++) {
                uint32_t o = g * 16 * VROWB + bo;
                uint32_t vh0[2], vh1[2], vl0[2], vl1[2];
                ldsm_x4(vh0[0], vh0[1], vh1[0], vh1[1], vbh + o);
                ldsm_x4(vl0[0], vl0[1], vl1[0], vl1[1], vbl + o);
                mma_16816(oacc[2 * g], ph, vh0);
                mma_16816(oacc[2 * g], pl, vh0);
                mma_16816(oacc[2 * g], ph, vl0);
                mma_16816(oacc[2 * g + 1], ph, vh1);
                mma_16816(oacc[2 * g + 1], pl, vh1);
                mma_16816(oacc[2 * g + 1], ph, vl1);
            }
        }
        __syncthreads();
    }

#pragma unroll
    for (int half = 0; half < 2; half++) {
        const int row = m0 + warp * 16 + (lane >> 2) + half * 8;
        const float inv = 1.0f / l_i[half];
        size_t off = (size_t)(b * TT + row) * NE + h * 128 + (lane & 3) * 2;
#pragma unroll
        for (int nt = 0; nt < 16; nt++) {
            uint32_t hw, lw;
            split2(oacc[nt][2 * half] * inv, oacc[nt][2 * half + 1] * inv, hw, lw);
            *(uint32_t*)&g_ath[off + nt * 8] = hw;
            *(uint32_t*)&g_atl[off + nt * 8] = lw;
        }
    }
}

// ---------------------------------------------------------------------------
extern "C" void kernel_launch(void* const* d_in, const int* in_sizes, int n_in,
                              void* d_out, int out_size) {
    const float* x      = (const float*)d_in[0];
    const float* w_attn = (const float*)d_in[1];
    const float* w_out  = (const float*)d_in[2];
    float* out = (float*)d_out;

    __nv_bfloat16 *xh, *xl, *wah, *wal, *woh, *wol, *ath, *atl;
    cudaGetSymbolAddress((void**)&xh, g_xh);
    cudaGetSymbolAddress((void**)&xl, g_xl);
    cudaGetSymbolAddress((void**)&wah, g_wah);
    cudaGetSymbolAddress((void**)&wal, g_wal);
    cudaGetSymbolAddress((void**)&woh, g_woh);
    cudaGetSymbolAddress((void**)&wol, g_wol);
    cudaGetSymbolAddress((void**)&ath, g_ath);
    cudaGetSymbolAddress((void**)&atl, g_atl);

    cudaFuncSetAttribute(gemm_bf16x3,
                         cudaFuncAttributeMaxDynamicSharedMemorySize, GEMM_SMEM);
    cudaFuncSetAttribute(gemm1_fused,
                         cudaFuncAttributeMaxDynamicSharedMemorySize, GEMM_SMEM);
    cudaFuncSetAttribute(mqa_flash_mma,
                         cudaFuncAttributeMaxDynamicSharedMemorySize, FLASH_SMEM);

    // 0) trig table + input splits
    trig_kernel<<<TT, 64>>>();
    split_kernel<<<(MROWS * NE / 4 + 255) / 256, 256>>>(x, xh, xl, MROWS * NE / 4);
    split_kernel<<<(QKV_LD * NE / 4 + 255) / 256, 256>>>(w_attn, wah, wal, QKV_LD * NE / 4);
    split_kernel<<<(NE * NE / 4 + 255) / 256, 256>>>(w_out, woh, wol, NE * NE / 4);

    // 1) qkv = x @ w_attn^T with fused RoPE/split/transpose epilogue
    gemm1_fused<<<dim3(QKV_LD / 128, MROWS / 256), 256, GEMM_SMEM>>>(
        xh, xl, wah, wal);

    // 2) attention (mma) -> att hi/lo bf16
    mqa_flash_mma<<<dim3(TT / 128, NH, BB), 256, FLASH_SMEM>>>();

    // 3) out = att @ w_out^T
    gemm_bf16x3<<<dim3(NE / 128, MROWS / 256), 256, GEMM_SMEM>>>(
        ath, atl, woh, wol, out, NE, NE);
}

// round 14
// speedup vs baseline: 1.0440x; 1.0440x over previous
#include <cuda_runtime.h>
#include <cuda_bf16.h>
#include <math.h>
#include <stdint.h>

// Problem constants
#define BB      2
#define TT      2048
#define NH      16
#define HD      128
#define NE      2048
#define QKV_LD  2304
#define MROWS   (BB*TT)         // 4096
#define KDIM    2048

// Scratch (__device__ globals; no allocation allowed)
__device__ float g_qkv[(size_t)MROWS * QKV_LD];
__device__ __nv_bfloat16 g_xh[(size_t)MROWS * NE];
__device__ __nv_bfloat16 g_xl[(size_t)MROWS * NE];
__device__ __nv_bfloat16 g_wah[(size_t)QKV_LD * NE];
__device__ __nv_bfloat16 g_wal[(size_t)QKV_LD * NE];
__device__ __nv_bfloat16 g_woh[(size_t)NE * NE];
__device__ __nv_bfloat16 g_wol[(size_t)NE * NE];
__device__ __nv_bfloat16 g_ath[(size_t)MROWS * NE];
__device__ __nv_bfloat16 g_atl[(size_t)MROWS * NE];
// flash inputs (post-rope, pre-split)
__device__ __nv_bfloat16 g_qh[(size_t)MROWS * NE];   // Q pre-scaled hi
__device__ __nv_bfloat16 g_ql[(size_t)MROWS * NE];   // Q pre-scaled lo
__device__ __nv_bfloat16 g_kh[(size_t)MROWS * HD];
__device__ __nv_bfloat16 g_kl[(size_t)MROWS * HD];
__device__ __nv_bfloat16 g_vth[(size_t)BB * HD * TT];  // V^T [b][d][key]
__device__ __nv_bfloat16 g_vtl[(size_t)BB * HD * TT];

// ---------------------------------------------------------------------------
// Helpers
// ---------------------------------------------------------------------------
__device__ __forceinline__ uint32_t smem_u32(const void* p) {
    uint32_t a;
    asm("{ .reg .u64 t; cvta.to.shared.u64 t, %1; cvt.u32.u64 %0, t; }"
        : "=r"(a) : "l"(p));
    return a;
}

__device__ __forceinline__ void ldsm_x4(uint32_t& r0, uint32_t& r1,
                                        uint32_t& r2, uint32_t& r3,
                                        uint32_t addr) {
    asm volatile("ldmatrix.sync.aligned.m8n8.x4.shared.b16 {%0,%1,%2,%3}, [%4];"
                 : "=r"(r0), "=r"(r1), "=r"(r2), "=r"(r3) : "r"(addr));
}

__device__ __forceinline__ void mma_16816(float* d, const uint32_t* a,
                                          const uint32_t* b) {
    asm volatile(
        "mma.sync.aligned.m16n8k16.row.col.f32.bf16.bf16.f32 "
        "{%0,%1,%2,%3}, {%4,%5,%6,%7}, {%8,%9}, {%0,%1,%2,%3};"
        : "+f"(d[0]), "+f"(d[1]), "+f"(d[2]), "+f"(d[3])
        : "r"(a[0]), "r"(a[1]), "r"(a[2]), "r"(a[3]), "r"(b[0]), "r"(b[1]));
}

#define CP_ASYNC16(dst, src) \
    asm volatile("cp.async.cg.shared.global [%0], [%1], 16;" :: "r"(dst), "l"(src))

// split (a,b) -> hi bf16x2 and lo bf16x2 packed as u32 (low half = a)
__device__ __forceinline__ void split2(float a, float b, uint32_t& h, uint32_t& l) {
    __nv_bfloat16 ha = __float2bfloat16(a), hb = __float2bfloat16(b);
    float ra = a - __bfloat162float(ha);
    float rb = b - __bfloat162float(hb);
    __nv_bfloat162 hv(ha, hb);
    __nv_bfloat162 lv(__float2bfloat16(ra), __float2bfloat16(rb));
    h = *(uint32_t*)&hv;
    l = *(uint32_t*)&lv;
}

// ---------------------------------------------------------------------------
// Split fp32 -> (hi, lo) bf16 (x, w_attn, w_out)
// ---------------------------------------------------------------------------
__global__ __launch_bounds__(256) void split_kernel(const float* __restrict__ src,
                                                    __nv_bfloat16* __restrict__ hi,
                                                    __nv_bfloat16* __restrict__ lo,
                                                    int n4) {
    int i = blockIdx.x * 256 + threadIdx.x;
    if (i >= n4) return;
    float4 v = ((const float4*)src)[i];
    uint32_t h0, l0, h1, l1;
    split2(v.x, v.y, h0, l0);
    split2(v.z, v.w, h1, l1);
    ((uint2*)hi)[i] = make_uint2(h0, h1);
    ((uint2*)lo)[i] = make_uint2(l0, l1);
}

// ---------------------------------------------------------------------------
// Warp-mma split-bf16 GEMM (verified round 11). CTA tile 256(M)x128(N),
// K-tile 64, 256 threads, 8 warps 4(M)x2(N), warp tile 64x64.
// C = Ah*Bh + Al*Bh + Ah*Bl. 2-stage cp.async. Bh-pass / Bl-pass split.
// ---------------------------------------------------------------------------
#define GKT 64
#define ROWB 144
#define A_TILE_B (256 * ROWB)            // 36864
#define B_TILE_B (128 * ROWB)            // 18432
#define STAGE_B (2 * A_TILE_B + 2 * B_TILE_B)   // 110592
#define GEMM_SMEM (2 * STAGE_B)          // 221184

__global__ __launch_bounds__(256, 1) void gemm_bf16x3(
    const __nv_bfloat16* __restrict__ Ah, const __nv_bfloat16* __restrict__ Al,
    const __nv_bfloat16* __restrict__ Bh, const __nv_bfloat16* __restrict__ Bl,
    float* __restrict__ C, int ldc, int K) {
    extern __shared__ char dynsmem[];
    const uint32_t sbase0 = smem_u32(dynsmem);

    const int tid = threadIdx.x;
    const int lane = tid & 31;
    const int warp = tid >> 5;           // 0..7
    const int wm = warp & 3;             // 0..3 -> M offset wm*64
    const int wn = warp >> 2;            // 0..1 -> N offset wn*64
    const int m0 = blockIdx.y * 256;
    const int n0 = blockIdx.x * 128;

    const __nv_bfloat16* gAh = Ah + (size_t)m0 * K;
    const __nv_bfloat16* gAl = Al + (size_t)m0 * K;
    const __nv_bfloat16* gBh = Bh + (size_t)n0 * K;
    const __nv_bfloat16* gBl = Bl + (size_t)n0 * K;

    auto load_stage = [&](int s, int kt) {
        const uint32_t st = sbase0 + s * STAGE_B;
#pragma unroll
        for (int i = 0; i < 8; i++) {
            const int f = i * 256 + tid;
            const int r = f >> 3;
            const int c = f & 7;
            CP_ASYNC16(st + r * ROWB + c * 16,
                       gAh + (size_t)r * K + kt * GKT + c * 8);
            CP_ASYNC16(st + A_TILE_B + r * ROWB + c * 16,
                       gAl + (size_t)r * K + kt * GKT + c * 8);
        }
#pragma unroll
        for (int i = 0; i < 4; i++) {
            const int f = i * 256 + tid;
            const int r = f >> 3;
            const int c = f & 7;
            CP_ASYNC16(st + 2 * A_TILE_B + r * ROWB + c * 16,
                       gBh + (size_t)r * K + kt * GKT + c * 8);
            CP_ASYNC16(st + 2 * A_TILE_B + B_TILE_B + r * ROWB + c * 16,
                       gBl + (size_t)r * K + kt * GKT + c * 8);
        }
        asm volatile("cp.async.commit_group;" ::: "memory");
    };

    float acc[32][4];                    // [mi*8 + nj][4]
#pragma unroll
    for (int t = 0; t < 32; t++)
#pragma unroll
        for (int j = 0; j < 4; j++) acc[t][j] = 0.0f;

    const int mat = lane >> 3;
    const int nkt = K / GKT;

    load_stage(0, 0);

    for (int kt = 0; kt < nkt; kt++) {
        const int s = kt & 1;
        if (kt + 1 < nkt) {
            load_stage((kt + 1) & 1, kt + 1);
            asm volatile("cp.async.wait_group 1;" ::: "memory");
        } else {
            asm volatile("cp.async.wait_group 0;" ::: "memory");
        }
        __syncthreads();

        const uint32_t st = sbase0 + s * STAGE_B;
        const uint32_t aBh = st + (wm * 64) * ROWB;
        const uint32_t aBl = aBh + A_TILE_B;
        const uint32_t bBh = st + 2 * A_TILE_B + (wn * 64) * ROWB;
        const uint32_t bBl = bBh + B_TILE_B;

#pragma unroll
        for (int ks = 0; ks < 4; ks++) {
            const uint32_t kc = ks * 32 + (lane >> 4) * 16;
            uint32_t ah[4][4], al[4][4];
#pragma unroll
            for (int mi = 0; mi < 4; mi++) {
                uint32_t ao = (mi * 16 + (lane & 15)) * ROWB + kc;
                ldsm_x4(ah[mi][0], ah[mi][1], ah[mi][2], ah[mi][3], aBh + ao);
                ldsm_x4(al[mi][0], al[mi][1], al[mi][2], al[mi][3], aBl + ao);
            }
            const uint32_t bo = ((mat >> 1) * 8 + (lane & 7)) * ROWB
                              + ks * 32 + (mat & 1) * 16;
            // pass 1: Bh -> Ah*Bh + Al*Bh
            {
                uint32_t bh[8][2];
#pragma unroll
                for (int g = 0; g < 4; g++) {
                    uint32_t o = g * 16 * ROWB + bo;
                    ldsm_x4(bh[2 * g][0], bh[2 * g][1], bh[2 * g + 1][0],
                            bh[2 * g + 1][1], bBh + o);
                }
#pragma unroll
                for (int mi = 0; mi < 4; mi++)
#pragma unroll
                    for (int nj = 0; nj < 8; nj++) {
                        mma_16816(acc[mi * 8 + nj], ah[mi], bh[nj]);
                        mma_16816(acc[mi * 8 + nj], al[mi], bh[nj]);
                    }
            }
            // pass 2: Bl -> Ah*Bl
            {
                uint32_t bl[8][2];
#pragma unroll
                for (int g = 0; g < 4; g++) {
                    uint32_t o = g * 16 * ROWB + bo;
                    ldsm_x4(bl[2 * g][0], bl[2 * g][1], bl[2 * g + 1][0],
                            bl[2 * g + 1][1], bBl + o);
                }
#pragma unroll
                for (int mi = 0; mi < 4; mi++)
#pragma unroll
                    for (int nj = 0; nj < 8; nj++)
                        mma_16816(acc[mi * 8 + nj], ah[mi], bl[nj]);
            }
        }
        __syncthreads();
    }

    const int rbase = m0 + wm * 64 + (lane >> 2);
    const int cbase = n0 + wn * 64 + (lane & 3) * 2;
#pragma unroll
    for (int mi = 0; mi < 4; mi++)
#pragma unroll
        for (int nj = 0; nj < 8; nj++) {
            float* c0 = C + (size_t)(rbase + mi * 16) * ldc + cbase + nj * 8;
            float* c1 = c0 + 8 * ldc;
            *(float2*)c0 = make_float2(acc[mi * 8 + nj][0], acc[mi * 8 + nj][1]);
            *(float2*)c1 = make_float2(acc[mi * 8 + nj][2], acc[mi * 8 + nj][3]);
        }
}

// ---------------------------------------------------------------------------
// Fused RoPE + Q/K hi-lo split (verified round 7).
// pos[j] = 10000 ** (-(4j+1)/128)
// ---------------------------------------------------------------------------
__global__ __launch_bounds__(64) void rope_split_kernel() {
    const int row = blockIdx.x;
    const int t = row & (TT - 1);
    const int j = threadIdx.x;
    const float scale = 0.08838834764831845f;

    double e = ((-4.0 * (double)j - 1.0) / 128.0) * 9.210340371976184;
    float freq = (float)exp(e);
    float ang = (float)t * freq;
    float c = cosf(ang);
    float s = sinf(ang);

    const float* base = g_qkv + (size_t)row * QKV_LD;
#pragma unroll
    for (int seg = 0; seg < 17; seg++) {
        const float* p = base + seg * 128;
        float x1 = p[j];
        float x2 = p[j + 64];
        float r1 = x1 * c - x2 * s;
        float r2 = x2 * c + x1 * s;
        if (seg < 16) {
            r1 *= scale; r2 *= scale;
            __nv_bfloat16 h1 = __float2bfloat16(r1);
            __nv_bfloat16 h2 = __float2bfloat16(r2);
            size_t o = (size_t)row * NE + seg * 128 + j;
            g_qh[o]      = h1;
            g_qh[o + 64] = h2;
            g_ql[o]      = __float2bfloat16(r1 - __bfloat162float(h1));
            g_ql[o + 64] = __float2bfloat16(r2 - __bfloat162float(h2));
        } else {
            __nv_bfloat16 h1 = __float2bfloat16(r1);
            __nv_bfloat16 h2 = __float2bfloat16(r2);
            size_t o = (size_t)row * HD + j;
            g_kh[o]      = h1;
            g_kh[o + 64] = h2;
            g_kl[o]      = __float2bfloat16(r1 - __bfloat162float(h1));
            g_kl[o + 64] = __float2bfloat16(r2 - __bfloat162float(h2));
        }
    }
}

// ---------------------------------------------------------------------------
// V transpose + split: g_qkv v-part [key][d] fp32 -> g_vth/g_vtl [b][d][key]
// ---------------------------------------------------------------------------
__global__ __launch_bounds__(256) void v_split_t() {
    const int blk = blockIdx.x;
    const int b = blk >> 5;
    const int t0 = (blk & 31) * 64;
    __shared__ float sv[64][132];
    const int tid = threadIdx.x;

#pragma unroll
    for (int i = 0; i < 8; i++) {
        int f = i * 256 + tid;
        int r = f >> 5;
        int c4 = (f & 31) * 4;
        float4 v = *(const float4*)
            &g_qkv[(size_t)(b * TT + t0 + r) * QKV_LD + 2176 + c4];
        sv[r][c4 + 0] = v.x; sv[r][c4 + 1] = v.y;
        sv[r][c4 + 2] = v.z; sv[r][c4 + 3] = v.w;
    }
    __syncthreads();

    const int d = tid >> 1;
    const int half = tid & 1;
    size_t orow = ((size_t)b * HD + d) * TT + t0 + half * 32;
#pragma unroll
    for (int j = 0; j < 4; j++) {
        uint32_t hw[4], lw[4];
#pragma unroll
        for (int u = 0; u < 4; u++) {
            int k0 = half * 32 + j * 8 + u * 2;
            split2(sv[k0][d], sv[k0 + 1][d], hw[u], lw[u]);
        }
        *(uint4*)&g_vth[orow + j * 8] = make_uint4(hw[0], hw[1], hw[2], hw[3]);
        *(uint4*)&g_vtl[orow + j * 8] = make_uint4(lw[0], lw[1], lw[2], lw[3]);
    }
}

// ---------------------------------------------------------------------------
// MMA flash MQA (verified round 6) + Q fragments hoisted to registers
// ---------------------------------------------------------------------------
#define CKEYS 64
#define NCH (TT / CKEYS)
#define QROWB 272
#define KROWB 272
#define VROWB 144
#define QTILE_B (128 * QROWB)
#define KTILE_B (CKEYS * KROWB)
#define VTILE_B (HD * VROWB)
#define FSTAGE_B (2 * KTILE_B + 2 * VTILE_B)
#define FLASH_SMEM (2 * QTILE_B + 2 * FSTAGE_B)

__global__ __launch_bounds__(256, 1) void mqa_flash_mma() {
    extern __shared__ char fsm[];
    const uint32_t sb = smem_u32(fsm);
    const int tid = threadIdx.x;
    const int lane = tid & 31;
    const int warp = tid >> 5;
    const int b = blockIdx.z;
    const int h = blockIdx.y;
    const int m0 = blockIdx.x * 128;

    {
        const __nv_bfloat16* gq = g_qh + (size_t)(b * TT + m0) * NE + h * 128;
        const __nv_bfloat16* gl = g_ql + (size_t)(b * TT + m0) * NE + h * 128;
#pragma unroll
        for (int i = 0; i < 8; i++) {
            int f = i * 256 + tid;
            int r = f >> 4;
            int c = f & 15;
            uint4 vh = *(const uint4*)(gq + (size_t)r * NE + c * 8);
            uint4 vl = *(const uint4*)(gl + (size_t)r * NE + c * 8);
            *(uint4*)(fsm + r * QROWB + c * 16) = vh;
            *(uint4*)(fsm + QTILE_B + r * QROWB + c * 16) = vl;
        }
    }
    __syncthreads();

    // Hoist Q fragments to registers: identical values for every chunk.
    uint32_t qfh[8][4], qfl[8][4];
#pragma unroll
    for (int ks = 0; ks < 8; ks++) {
        uint32_t ao = (warp * 16 + (lane & 15)) * QROWB
                    + ks * 32 + (lane >> 4) * 16;
        ldsm_x4(qfh[ks][0], qfh[ks][1], qfh[ks][2], qfh[ks][3], sb + ao);
        ldsm_x4(qfl[ks][0], qfl[ks][1], qfl[ks][2], qfl[ks][3],
                sb + QTILE_B + ao);
    }

    auto load_stage = [&](int s, int kb) {
        uint32_t st = sb + 2 * QTILE_B + s * FSTAGE_B;
        const __nv_bfloat16* kh = g_kh + (size_t)(b * TT + kb * CKEYS) * HD;
        const __nv_bfloat16* kl = g_kl + (size_t)(b * TT + kb * CKEYS) * HD;
#pragma unroll
        for (int i = 0; i < 4; i++) {
            int f = i * 256 + tid;
            int r = f >> 4;
            int c = f & 15;
            CP_ASYNC16(st + r * KROWB + c * 16, kh + (size_t)r * HD + c * 8);
            CP_ASYNC16(st + KTILE_B + r * KROWB + c * 16, kl + (size_t)r * HD + c * 8);
        }
        const __nv_bfloat16* vh = g_vth + (size_t)b * HD * TT + kb * CKEYS;
        const __nv_bfloat16* vl = g_vtl + (size_t)b * HD * TT + kb * CKEYS;
#pragma unroll
        for (int i = 0; i < 4; i++) {
            int f = i * 256 + tid;
            int r = f >> 3;
            int c = f & 7;
            CP_ASYNC16(st + 2 * KTILE_B + r * VROWB + c * 16,
                       vh + (size_t)r * TT + c * 8);
            CP_ASYNC16(st + 2 * KTILE_B + VTILE_B + r * VROWB + c * 16,
                       vl + (size_t)r * TT + c * 8);
        }
        asm volatile("cp.async.commit_group;" ::: "memory");
    };

    float oacc[16][4];
#pragma unroll
    for (int t = 0; t < 16; t++)
#pragma unroll
        for (int j = 0; j < 4; j++) oacc[t][j] = 0.0f;
    float m_i[2] = {-INFINITY, -INFINITY};
    float l_i[2] = {0.0f, 0.0f};

    load_stage(0, 0);

    for (int kb = 0; kb < NCH; kb++) {
        const int s = kb & 1;
        if (kb + 1 < NCH) {
            load_stage((kb + 1) & 1, kb + 1);
            asm volatile("cp.async.wait_group 1;" ::: "memory");
        } else {
            asm volatile("cp.async.wait_group 0;" ::: "memory");
        }
        __syncthreads();

        const uint32_t st = sb + 2 * QTILE_B + s * FSTAGE_B;
        const int mat = lane >> 3;

        float sfr[8][4];
#pragma unroll
        for (int t = 0; t < 8; t++)
#pragma unroll
            for (int j = 0; j < 4; j++) sfr[t][j] = 0.0f;

#pragma unroll
        for (int ks = 0; ks < 8; ks++) {
            uint32_t bo = ((mat >> 1) * 8 + (lane & 7)) * KROWB
                        + ks * 32 + (mat & 1) * 16;
            uint32_t bh[8][2], bl[8][2];
#pragma unroll
            for (int g = 0; g < 4; g++) {
                uint32_t o = g * 16 * KROWB + bo;
                ldsm_x4(bh[2 * g][0], bh[2 * g][1], bh[2 * g + 1][0],
                        bh[2 * g + 1][1], st + o);
                ldsm_x4(bl[2 * g][0], bl[2 * g][1], bl[2 * g + 1][0],
                        bl[2 * g + 1][1], st + KTILE_B + o);
            }
#pragma unroll
            for (int nj = 0; nj < 8; nj++) {
                mma_16816(sfr[nj], qfh[ks], bh[nj]);
                mma_16816(sfr[nj], qfh[ks], bl[nj]);
                mma_16816(sfr[nj], qfl[ks], bh[nj]);
            }
        }

#pragma unroll
        for (int half = 0; half < 2; half++) {
            float mx = -INFINITY;
#pragma unroll
            for (int nj = 0; nj < 8; nj++)
                mx = fmaxf(mx, fmaxf(sfr[nj][2 * half], sfr[nj][2 * half + 1]));
            mx = fmaxf(mx, __shfl_xor_sync(0xffffffffu, mx, 1));
            mx = fmaxf(mx, __shfl_xor_sync(0xffffffffu, mx, 2));
            float mn = fmaxf(m_i[half], mx);
            float corr = __expf(m_i[half] - mn);
            m_i[half] = mn;
            float sum = 0.0f;
#pragma unroll
            for (int nj = 0; nj < 8; nj++) {
                float p0 = __expf(sfr[nj][2 * half] - mn);
                float p1 = __expf(sfr[nj][2 * half + 1] - mn);
                sfr[nj][2 * half] = p0;
                sfr[nj][2 * half + 1] = p1;
                sum += p0 + p1;
            }
            sum += __shfl_xor_sync(0xffffffffu, sum, 1);
            sum += __shfl_xor_sync(0xffffffffu, sum, 2);
            l_i[half] = l_i[half] * corr + sum;
#pragma unroll
            for (int nt = 0; nt < 16; nt++) {
                oacc[nt][2 * half] *= corr;
                oacc[nt][2 * half + 1] *= corr;
            }
        }

        const uint32_t vbh = st + 2 * KTILE_B;
        const uint32_t vbl = vbh + VTILE_B;
#pragma unroll
        for (int kk = 0; kk < 4; kk++) {
            uint32_t ph[4], pl[4];
            split2(sfr[2 * kk][0], sfr[2 * kk][1], ph[0], pl[0]);
            split2(sfr[2 * kk][2], sfr[2 * kk][3], ph[1], pl[1]);
            split2(sfr[2 * kk + 1][0], sfr[2 * kk + 1][1], ph[2], pl[2]);
            split2(sfr[2 * kk + 1][2], sfr[2 * kk + 1][3], ph[3], pl[3]);

            uint32_t bo = ((mat >> 1) * 8 + (lane & 7)) * VROWB
                        + kk * 32 + (mat & 1) * 16;
#pragma unroll
            for (int g = 0; g < 8; g++) {
                uint32_t o = g * 16 * VROWB + bo;
                uint32_t vh0[2], vh1[2], vl0[2], vl1[2];
                ldsm_x4(vh0[0], vh0[1], vh1[0], vh1[1], vbh + o);
                ldsm_x4(vl0[0], vl0[1], vl1[0], vl1[1], vbl + o);
                mma_16816(oacc[2 * g], ph, vh0);
                mma_16816(oacc[2 * g], pl, vh0);
                mma_16816(oacc[2 * g], ph, vl0);
                mma_16816(oacc[2 * g + 1], ph, vh1);
                mma_16816(oacc[2 * g + 1], pl, vh1);
                mma_16816(oacc[2 * g + 1], ph, vl1);
            }
        }
        __syncthreads();
    }

#pragma unroll
    for (int half = 0; half < 2; half++) {
        const int row = m0 + warp * 16 + (lane >> 2) + half * 8;
        const float inv = 1.0f / l_i[half];
        size_t off = (size_t)(b * TT + row) * NE + h * 128 + (lane & 3) * 2;
#pragma unroll
        for (int nt = 0; nt < 16; nt++) {
            uint32_t hw, lw;
            split2(oacc[nt][2 * half] * inv, oacc[nt][2 * half + 1] * inv, hw, lw);
            *(uint32_t*)&g_ath[off + nt * 8] = hw;
            *(uint32_t*)&g_atl[off + nt * 8] = lw;
        }
    }
}

// ---------------------------------------------------------------------------
extern "C" void kernel_launch(void* const* d_in, const int* in_sizes, int n_in,
                              void* d_out, int out_size) {
    const float* x      = (const float*)d_in[0];
    const float* w_attn = (const float*)d_in[1];
    const float* w_out  = (const float*)d_in[2];
    float* out = (float*)d_out;

    float* qkv = nullptr;
    __nv_bfloat16 *xh, *xl, *wah, *wal, *woh, *wol, *ath, *atl;
    cudaGetSymbolAddress((void**)&qkv, g_qkv);
    cudaGetSymbolAddress((void**)&xh, g_xh);
    cudaGetSymbolAddress((void**)&xl, g_xl);
    cudaGetSymbolAddress((void**)&wah, g_wah);
    cudaGetSymbolAddress((void**)&wal, g_wal);
    cudaGetSymbolAddress((void**)&woh, g_woh);
    cudaGetSymbolAddress((void**)&wol, g_wol);
    cudaGetSymbolAddress((void**)&ath, g_ath);
    cudaGetSymbolAddress((void**)&atl, g_atl);

    cudaFuncSetAttribute(gemm_bf16x3,
                         cudaFuncAttributeMaxDynamicSharedMemorySize, GEMM_SMEM);
    cudaFuncSetAttribute(mqa_flash_mma,
                         cudaFuncAttributeMaxDynamicSharedMemorySize, FLASH_SMEM);

    // 0) split inputs
    split_kernel<<<(MROWS * NE / 4 + 255) / 256, 256>>>(x, xh, xl, MROWS * NE / 4);
    split_kernel<<<(QKV_LD * NE / 4 + 255) / 256, 256>>>(w_attn, wah, wal, QKV_LD * NE / 4);
    split_kernel<<<(NE * NE / 4 + 255) / 256, 256>>>(w_out, woh, wol, NE * NE / 4);

    // 1) qkv = x @ w_attn^T  (CTA tile 256x128)
    gemm_bf16x3<<<dim3(QKV_LD / 128, MROWS / 256), 256, GEMM_SMEM>>>(
        xh, xl, wah, wal, qkv, QKV_LD, NE);

    // 2) fused RoPE + Q/K split
    rope_split_kernel<<<MROWS, 64>>>();

    // 3) V transpose + split
    v_split_t<<<BB * (TT / 64), 256>>>();

    // 4) attention (mma) -> att hi/lo bf16
    mqa_flash_mma<<<dim3(TT / 128, NH, BB), 256, FLASH_SMEM>>>();

    // 5) out = att @ w_out^T  (CTA tile 256x128)
    gemm_bf16x3<<<dim3(NE / 128, MROWS / 256), 256, GEMM_SMEM>>>(
        ath, atl, woh, wol, out, NE, NE);
}